// round 1
// baseline (speedup 1.0000x reference)
#include <cuda_runtime.h>

#define CM_B    64
#define CM_T    256
#define CM_NI   512
#define CM_NO   512
#define CM_NOBS 128
#define WARPS_PER_BLOCK 8

typedef unsigned long long u64;

// ---- packed f32x2 helpers (sm_100+ PTX; FFMA2 is not emitted by ptxas from C++) ----
__device__ __forceinline__ u64 pk2(float lo, float hi) {
    u64 r; asm("mov.b64 %0, {%1, %2};" : "=l"(r) : "f"(lo), "f"(hi)); return r;
}
__device__ __forceinline__ float2 upk2(u64 v) {
    float2 f; asm("mov.b64 {%0, %1}, %2;" : "=f"(f.x), "=f"(f.y) : "l"(v)); return f;
}
__device__ __forceinline__ u64 ffma2(u64 a, u64 b, u64 c) {
    u64 d; asm("fma.rn.f32x2 %0, %1, %2, %3;" : "=l"(d) : "l"(a), "l"(b), "l"(c)); return d;
}

// One warp = one (batch, observed-slot) row recurrence.
// w row (512 f32) lives in registers: 16 floats/lane = 8 packed f32x2.
__global__ __launch_bounds__(WARPS_PER_BLOCK * 32)
void circuit_kernel(const float* __restrict__ X,
                    const float* __restrict__ Wi,
                    const int*   __restrict__ obs,
                    float*       __restrict__ out) {
    const int b    = blockIdx.x;           // batch
    const int g    = blockIdx.y;           // row group
    const int warp = threadIdx.x >> 5;
    const int lane = threadIdx.x & 31;
    const int j    = g * WARPS_PER_BLOCK + warp;   // observed slot 0..127
    const int o    = __ldg(&obs[j]);

    // Load this row of W_init (only observed rows ever matter).
    const float4* wp = (const float4*)(Wi + ((size_t)b * CM_NO + o) * CM_NI + lane * 16);
    float4 wa = __ldg(wp + 0), wb = __ldg(wp + 1), wc = __ldg(wp + 2), wd = __ldg(wp + 3);
    u64 w[8];
    w[0] = pk2(wa.x, wa.y); w[1] = pk2(wa.z, wa.w);
    w[2] = pk2(wb.x, wb.y); w[3] = pk2(wb.z, wb.w);
    w[4] = pk2(wc.x, wc.y); w[5] = pk2(wc.z, wc.w);
    w[6] = pk2(wd.x, wd.y); w[7] = pk2(wd.z, wd.w);

    const float4* xbase = (const float4*)(X + (size_t)b * CM_T * CM_NI + lane * 16);
    float* op = out + (size_t)b * CM_T * CM_NOBS + j;

    #pragma unroll 1
    for (int t = 0; t < CM_T; ++t) {
        const float4* xp = xbase + t * (CM_NI / 4);
        float4 x0 = __ldg(xp + 0), x1 = __ldg(xp + 1);
        float4 x2 = __ldg(xp + 2), x3 = __ldg(xp + 3);
        u64 xx[8];
        xx[0] = pk2(x0.x, x0.y); xx[1] = pk2(x0.z, x0.w);
        xx[2] = pk2(x1.x, x1.y); xx[3] = pk2(x1.z, x1.w);
        xx[4] = pk2(x2.x, x2.y); xx[5] = pk2(x2.z, x2.w);
        xx[6] = pk2(x3.x, x3.y); xx[7] = pk2(x3.z, x3.w);

        // dot(w, x_t) over this lane's 16 elements, 2 packed accumulators for ILP
        u64 acc0 = pk2(0.f, 0.f), acc1 = pk2(0.f, 0.f);
        #pragma unroll
        for (int k = 0; k < 8; k += 2) {
            acc0 = ffma2(w[k],     xx[k],     acc0);
            acc1 = ffma2(w[k + 1], xx[k + 1], acc1);
        }
        float2 s0 = upk2(acc0), s1 = upk2(acc1);
        float pre = (s0.x + s0.y) + (s1.x + s1.y);

        // butterfly reduce across warp -> all lanes hold full dot
        #pragma unroll
        for (int d = 16; d > 0; d >>= 1)
            pre += __shfl_xor_sync(0xffffffffu, pre, d);

        const float y = __fdividef(1.0f, 1.0f + __expf(-pre));
        if (lane == 0) op[t * CM_NOBS] = y;

        // w += ETA * y * x_t
        const float c = 0.01f * y;
        const u64 c2 = pk2(c, c);
        #pragma unroll
        for (int k = 0; k < 8; ++k)
            w[k] = ffma2(c2, xx[k], w[k]);
    }
}

extern "C" void kernel_launch(void* const* d_in, const int* in_sizes, int n_in,
                              void* d_out, int out_size) {
    const float* X   = (const float*)d_in[0];
    const float* Wi  = (const float*)d_in[1];
    const int*   obs = (const int*)d_in[2];
    float*       out = (float*)d_out;

    dim3 grid(CM_B, CM_NOBS / WARPS_PER_BLOCK);   // 64 x 16 = 1024 blocks
    circuit_kernel<<<grid, WARPS_PER_BLOCK * 32>>>(X, Wi, obs, out);
}

// round 3
// speedup vs baseline: 3.2099x; 3.2099x over previous
#include <cuda_runtime.h>

#define CM_B    64
#define CM_T    256
#define CM_NI   512
#define CM_NO   512
#define CM_NOBS 128
#define ROWS_PER_WARP   4
#define WARPS_PER_BLOCK 4
#define THREADS (WARPS_PER_BLOCK * 32)

typedef unsigned long long u64;

static_assert(sizeof(ulonglong2) == 16, "ulonglong2 must be 16B");
#define X_ROW_U2 (CM_NI / 4)   // 128 ulonglong2 per 512-float row

__device__ __forceinline__ u64 pk2(float lo, float hi) {
    u64 r; asm("mov.b64 %0, {%1, %2};" : "=l"(r) : "f"(lo), "f"(hi)); return r;
}
__device__ __forceinline__ float2 upk2(u64 v) {
    float2 f; asm("mov.b64 {%0, %1}, %2;" : "=f"(f.x), "=f"(f.y) : "l"(v)); return f;
}
__device__ __forceinline__ u64 ffma2(u64 a, u64 b, u64 c) {
    u64 d; asm("fma.rn.f32x2 %0, %1, %2, %3;" : "=l"(d) : "l"(a), "l"(b), "l"(c)); return d;
}

// One warp = 4 contiguous observed slots of one batch.
// Lane l owns float4-chunks {k*32 + l, k=0..3} of each 512-float vector (coalesced).
__global__ __launch_bounds__(THREADS, 4)
void circuit_kernel(const float* __restrict__ X,
                    const float* __restrict__ Wi,
                    const int*   __restrict__ obs,
                    float*       __restrict__ out) {
    const int b    = blockIdx.x;
    const int warp = threadIdx.x >> 5;
    const int lane = threadIdx.x & 31;
    const int wg   = blockIdx.y * WARPS_PER_BLOCK + warp;  // 0..31
    const int j0   = wg * ROWS_PER_WARP;                   // first observed slot

    // ---- load W rows for the 4 observed outputs (coalesced lane layout) ----
    u64 w[ROWS_PER_WARP][8];
    #pragma unroll
    for (int r = 0; r < ROWS_PER_WARP; ++r) {
        const int o = __ldg(&obs[j0 + r]);
        const ulonglong2* wp =
            (const ulonglong2*)(Wi + ((size_t)b * CM_NO + o) * CM_NI) + lane;
        #pragma unroll
        for (int k = 0; k < 4; ++k) {
            ulonglong2 v = __ldg(wp + k * 32);
            w[r][2 * k]     = v.x;
            w[r][2 * k + 1] = v.y;
        }
    }

    const ulonglong2* xb =
        (const ulonglong2*)(X + (size_t)b * CM_T * CM_NI) + lane;
    float* op = out + (size_t)b * CM_T * CM_NOBS + j0;

    // prefetch x_0
    u64 xx[8];
    #pragma unroll
    for (int k = 0; k < 4; ++k) {
        ulonglong2 v = __ldg(xb + k * 32);
        xx[2 * k] = v.x; xx[2 * k + 1] = v.y;
    }

    #pragma unroll 1
    for (int t = 0; t < CM_T; ++t) {
        // prefetch x_{t+1} while this step computes (clamped: no UB, no OOB)
        const int tn = (t + 1 < CM_T) ? (t + 1) : t;
        const ulonglong2* xp = xb + tn * X_ROW_U2;
        u64 xn[8];
        #pragma unroll
        for (int k = 0; k < 4; ++k) {
            ulonglong2 v = __ldg(xp + k * 32);
            xn[2 * k] = v.x; xn[2 * k + 1] = v.y;
        }

        // ---- 4 dot products (packed f32x2, 2 acc chains each) ----
        float pre[ROWS_PER_WARP];
        #pragma unroll
        for (int r = 0; r < ROWS_PER_WARP; ++r) {
            u64 a0 = pk2(0.f, 0.f), a1 = pk2(0.f, 0.f);
            #pragma unroll
            for (int k = 0; k < 8; k += 2) {
                a0 = ffma2(w[r][k],     xx[k],     a0);
                a1 = ffma2(w[r][k + 1], xx[k + 1], a1);
            }
            float2 s0 = upk2(a0), s1 = upk2(a1);
            pre[r] = (s0.x + s0.y) + (s1.x + s1.y);
        }

        // ---- butterfly reductions (4 independent chains interleave) ----
        #pragma unroll
        for (int d = 16; d > 0; d >>= 1) {
            #pragma unroll
            for (int r = 0; r < ROWS_PER_WARP; ++r)
                pre[r] += __shfl_xor_sync(0xffffffffu, pre[r], d);
        }

        // ---- sigmoid + output ----
        float y[ROWS_PER_WARP];
        #pragma unroll
        for (int r = 0; r < ROWS_PER_WARP; ++r)
            y[r] = __fdividef(1.0f, 1.0f + __expf(-pre[r]));

        if (lane == 0)
            *(float4*)(op + t * CM_NOBS) = make_float4(y[0], y[1], y[2], y[3]);

        // ---- rank-1 updates: w_r += 0.01*y_r * x_t ----
        #pragma unroll
        for (int r = 0; r < ROWS_PER_WARP; ++r) {
            const float c = 0.01f * y[r];
            const u64 c2 = pk2(c, c);
            #pragma unroll
            for (int k = 0; k < 8; ++k)
                w[r][k] = ffma2(c2, xx[k], w[r][k]);
        }

        #pragma unroll
        for (int k = 0; k < 8; ++k) xx[k] = xn[k];
    }
}

extern "C" void kernel_launch(void* const* d_in, const int* in_sizes, int n_in,
                              void* d_out, int out_size) {
    const float* X   = (const float*)d_in[0];
    const float* Wi  = (const float*)d_in[1];
    const int*   obs = (const int*)d_in[2];
    float*       out = (float*)d_out;

    dim3 grid(CM_B, CM_NOBS / (ROWS_PER_WARP * WARPS_PER_BLOCK));  // 64 x 8
    circuit_kernel<<<grid, THREADS>>>(X, Wi, obs, out);
}

// round 4
// speedup vs baseline: 4.0988x; 1.2769x over previous
#include <cuda_runtime.h>

#define CM_B    64
#define CM_T    256
#define CM_NI   512
#define CM_NO   512
#define CM_NOBS 128
#define ROWS_PER_WARP   4
#define WARPS_PER_BLOCK 4
#define THREADS (WARPS_PER_BLOCK * 32)
#define X_ROW_U2 (CM_NI / 4)   // 128 ulonglong2 per 512-float row

typedef unsigned long long u64;

__device__ __forceinline__ u64 pk2(float lo, float hi) {
    u64 r; asm("mov.b64 %0, {%1, %2};" : "=l"(r) : "f"(lo), "f"(hi)); return r;
}
__device__ __forceinline__ float2 upk2(u64 v) {
    float2 f; asm("mov.b64 {%0, %1}, %2;" : "=f"(f.x), "=f"(f.y) : "l"(v)); return f;
}
__device__ __forceinline__ u64 ffma2(u64 a, u64 b, u64 c) {
    u64 d; asm("fma.rn.f32x2 %0, %1, %2, %3;" : "=l"(d) : "l"(a), "l"(b), "l"(c)); return d;
}
__device__ __forceinline__ u64 fadd2(u64 a, u64 b) {
    u64 d; asm("add.rn.f32x2 %0, %1, %2;" : "=l"(d) : "l"(a), "l"(b)); return d;
}

// One warp = 4 contiguous observed slots of one batch.
// Lane l owns float4-chunks {k*32 + l, k=0..3} of each 512-float vector.
__global__ __launch_bounds__(THREADS, 4)
void circuit_kernel(const float* __restrict__ X,
                    const float* __restrict__ Wi,
                    const int*   __restrict__ obs,
                    float*       __restrict__ out) {
    const int b    = blockIdx.x;
    const int warp = threadIdx.x >> 5;
    const int lane = threadIdx.x & 31;
    const int wg   = blockIdx.y * WARPS_PER_BLOCK + warp;  // 0..31
    const int j0   = wg * ROWS_PER_WARP;                   // first observed slot

    const int  g       = lane >> 3;            // this lane's row group (0..3)
    const bool sel1    = (g == 1);
    const bool sel2    = (g == 2);
    const bool sel3    = (g == 3);
    const bool st_pred = (lane & 7) == 0;      // lanes 0,8,16,24 store rows 0..3

    // ---- load W rows (coalesced lane layout) ----
    u64 w[ROWS_PER_WARP][8];
    #pragma unroll
    for (int r = 0; r < ROWS_PER_WARP; ++r) {
        const int o = __ldg(&obs[j0 + r]);
        const ulonglong2* wp =
            (const ulonglong2*)(Wi + ((size_t)b * CM_NO + o) * CM_NI) + lane;
        #pragma unroll
        for (int k = 0; k < 4; ++k) {
            ulonglong2 v = __ldg(wp + k * 32);
            w[r][2 * k]     = v.x;
            w[r][2 * k + 1] = v.y;
        }
    }

    const ulonglong2* xb = (const ulonglong2*)(X + (size_t)b * CM_T * CM_NI) + lane;
    float* opl = out + (size_t)b * CM_T * CM_NOBS + j0 + g;   // used iff st_pred

    // preload x_0 into buffer A; pf points at row 1
    u64 xA[8], xB[8];
    #pragma unroll
    for (int k = 0; k < 4; ++k) {
        ulonglong2 v = __ldg(xb + k * 32);
        xA[2 * k] = v.x; xA[2 * k + 1] = v.y;
    }
    const ulonglong2* pf = xb + X_ROW_U2;

    // one recurrence step: compute with cur, prefetch next row into nxt
    auto step = [&](const u64* __restrict__ cur, u64* __restrict__ nxt, bool pre) {
        if (pre) {
            #pragma unroll
            for (int k = 0; k < 4; ++k) {
                ulonglong2 v = __ldg(pf + k * 32);
                nxt[2 * k] = v.x; nxt[2 * k + 1] = v.y;
            }
        }
        pf += X_ROW_U2;

        // 4 dot products, 2 packed chains each
        float pre4[ROWS_PER_WARP];
        #pragma unroll
        for (int r = 0; r < ROWS_PER_WARP; ++r) {
            u64 a0 = ffma2(w[r][0], cur[0], pk2(0.f, 0.f));
            u64 a1 = ffma2(w[r][1], cur[1], pk2(0.f, 0.f));
            #pragma unroll
            for (int k = 2; k < 8; k += 2) {
                a0 = ffma2(w[r][k],     cur[k],     a0);
                a1 = ffma2(w[r][k + 1], cur[k + 1], a1);
            }
            float2 s = upk2(fadd2(a0, a1));
            pre4[r] = s.x + s.y;
        }

        // butterfly d=16,8 on all rows -> 8 partial classes per row
        #pragma unroll
        for (int d = 16; d >= 8; d >>= 1) {
            #pragma unroll
            for (int r = 0; r < ROWS_PER_WARP; ++r)
                pre4[r] += __shfl_xor_sync(0xffffffffu, pre4[r], d);
        }

        // each 8-lane group finishes its own row
        float v = pre4[0];
        if (sel1) v = pre4[1];
        if (sel2) v = pre4[2];
        if (sel3) v = pre4[3];
        v += __shfl_xor_sync(0xffffffffu, v, 4);
        v += __shfl_xor_sync(0xffffffffu, v, 2);
        v += __shfl_xor_sync(0xffffffffu, v, 1);

        const float y = __fdividef(1.0f, 1.0f + __expf(-v));
        if (st_pred) *opl = y;
        opl += CM_NOBS;

        // broadcast 0.01*y per row, rank-1 updates
        const float c  = 0.01f * y;
        const float c0 = __shfl_sync(0xffffffffu, c, 0);
        const float c1 = __shfl_sync(0xffffffffu, c, 8);
        const float c2 = __shfl_sync(0xffffffffu, c, 16);
        const float c3 = __shfl_sync(0xffffffffu, c, 24);
        u64 cc[ROWS_PER_WARP] = { pk2(c0, c0), pk2(c1, c1), pk2(c2, c2), pk2(c3, c3) };
        #pragma unroll
        for (int r = 0; r < ROWS_PER_WARP; ++r)
            #pragma unroll
            for (int k = 0; k < 8; ++k)
                w[r][k] = ffma2(cc[r], cur[k], w[r][k]);
    };

    #pragma unroll 1
    for (int t = 0; t < CM_T; t += 2) {
        step(xA, xB, true);              // t:   compute row t,  prefetch t+1
        step(xB, xA, t + 2 < CM_T);      // t+1: compute,        prefetch t+2
    }
}

extern "C" void kernel_launch(void* const* d_in, const int* in_sizes, int n_in,
                              void* d_out, int out_size) {
    const float* X   = (const float*)d_in[0];
    const float* Wi  = (const float*)d_in[1];
    const int*   obs = (const int*)d_in[2];
    float*       out = (float*)d_out;

    dim3 grid(CM_B, CM_NOBS / (ROWS_PER_WARP * WARPS_PER_BLOCK));  // 64 x 8
    circuit_kernel<<<grid, THREADS>>>(X, Wi, obs, out);
}